// round 14
// baseline (speedup 1.0000x reference)
#include <cuda_runtime.h>
#include <cuda_fp16.h>
#include <cstdint>
#include <cstdio>

// Problem constants
#define E   160
#define BB  8
#define NN  4096
#define BN  (BB*NN)          // 32768 tokens
#define DINN 15
#define BSTR 162             // smem B row stride for gemm128 (floats)

// ---------------- static device scratch (allocation-free rule) ----------------
__device__ float g_cproj[6 * E * E];       // fused inner projection matrices [k][j]
__device__ float g_mfin [6 * E * E];       // fused final projection matrices [k][j]
__device__ float g_bfin [6 * E];           // fused final biases
__device__ float g_bv   [2 * E];           // v-bias with f_out_w folded in
// mats 0-5 (final q/k/v' h0,h1): PANEL-major [mat][ks][n][16 perm]
// mats 6-11 (cproj): row-major [n][k perm] (consumed by gemm6_mma)
__device__ __half g_wh  [12 * E * E];
__device__ __half g_px  [6ull * BN * E];               // projected X, fp16
__device__ __half g_obuf[(size_t)BN * 32 * E];         // inner attn out, TOKEN-major fp16
__device__ float g_pooled[(size_t)BN * E];

// ---------------- f32x2 helpers ----------------
__device__ __forceinline__ unsigned long long fma2(unsigned long long a,
                                                   unsigned long long b,
                                                   unsigned long long c) {
    unsigned long long d;
    asm("fma.rn.f32x2 %0, %1, %2, %3;" : "=l"(d) : "l"(a), "l"(b), "l"(c));
    return d;
}
__device__ __forceinline__ unsigned long long pack2(float x, float y) {
    unsigned long long r;
    asm("mov.b64 %0, {%1,%2};" : "=l"(r) : "f"(x), "f"(y));
    return r;
}
__device__ __forceinline__ float2 unpack2(unsigned long long v) {
    float2 f;
    asm("mov.b64 {%0,%1}, %2;" : "=f"(f.x), "=f"(f.y) : "l"(v));
    return f;
}

// ---------------- mma.sync m16n8k16 fp16->fp32 (validated frag ordering) -------
__device__ __forceinline__ void mma16816(float* c, uint32_t a0, uint32_t a1,
                                         uint32_t a2, uint32_t a3,
                                         uint32_t b0, uint32_t b1) {
    asm volatile(
        "mma.sync.aligned.m16n8k16.row.col.f32.f16.f16.f32 "
        "{%0,%1,%2,%3}, {%4,%5,%6,%7}, {%8,%9}, {%0,%1,%2,%3};\n"
        : "+f"(c[0]), "+f"(c[1]), "+f"(c[2]), "+f"(c[3])
        : "r"(a0), "r"(a1), "r"(a2), "r"(a3), "r"(b0), "r"(b1));
}

// ---------------- ldmatrix helpers ----------------
__device__ __forceinline__ uint32_t cvta_smem(const void* p) {
    return (uint32_t)__cvta_generic_to_shared(p);
}
__device__ __forceinline__ void ldsm_x4(uint32_t& r0, uint32_t& r1, uint32_t& r2,
                                        uint32_t& r3, uint32_t a) {
    asm volatile("ldmatrix.sync.aligned.m8n8.x4.shared.b16 {%0,%1,%2,%3}, [%4];"
                 : "=r"(r0), "=r"(r1), "=r"(r2), "=r"(r3) : "r"(a));
}
__device__ __forceinline__ void ldsm_x2t(uint32_t& r0, uint32_t& r1, uint32_t a) {
    asm volatile("ldmatrix.sync.aligned.m8n8.x2.trans.shared.b16 {%0,%1}, [%2];"
                 : "=r"(r0), "=r"(r1) : "r"(a));
}

__device__ __forceinline__ uint32_t H2F(float a, float b) {
    __half2 h = __floats2half2_rn(a, b);
    return *reinterpret_cast<uint32_t*>(&h);
}

// k-permutation within a 16-k group so mma k-pairs are contiguous words
__device__ __forceinline__ int kperm(int l) {
    return (l < 8) ? (((l >> 1) << 2) + (l & 1))
                   : ((((l - 8) >> 1) << 2) + 2 + (l & 1));
}

// ---------------- setup1: all fused fp32 matrices + fused biases ----------------
__global__ void setup1(
    const float* __restrict__ iWq, const float* __restrict__ iWk, const float* __restrict__ iWv,
    const float* __restrict__ oWq, const float* __restrict__ oWk, const float* __restrict__ oWv,
    const float* __restrict__ i_in_w, const float* __restrict__ o_in_w,
    const float* __restrict__ f_in_w, const float* __restrict__ i_out_w,
    const float* __restrict__ o_out_w,
    const float* __restrict__ f_in_b,
    const float* __restrict__ i_out_b, const float* __restrict__ o_out_b)
{
    __shared__ float col[E];
    int m = blockIdx.y, r = blockIdx.x, j = threadIdx.x;
    if (m < 6) {
        const float* W = (m == 0) ? iWq : (m == 1) ? iWk : (m == 2) ? iWv
                       : (m == 3) ? oWq : (m == 4) ? oWk : oWv;
        const float* inw = ((m < 3) ? i_in_w : o_in_w) + (size_t)(m % 3) * E * E;
        col[j] = W[r * E + j];
        __syncthreads();
        float s = 0.f;
        #pragma unroll 8
        for (int tt = 0; tt < E; tt++) s += col[tt] * inw[j * E + tt];
        g_cproj[(size_t)m * E * E + r * E + j] = s;
    } else if (m < 12) {
        int mf = m - 6;
        int f = mf >> 1;
        const float* ow = (mf & 1) ? o_out_w : i_out_w;
        col[j] = ow[j * E + r];
        __syncthreads();
        float s = 0.f;
        #pragma unroll 8
        for (int c = 0; c < E; c++) s += col[c] * f_in_w[(f * E + j) * E + c];
        g_mfin[(size_t)mf * E * E + r * E + j] = s;
    } else {
        if (r < 6) {
            int f = r >> 1;
            const float* ob = (r & 1) ? o_out_b : i_out_b;
            float s = f_in_b[f * E + j];
            #pragma unroll 8
            for (int c = 0; c < E; c++) s += ob[c] * f_in_w[(f * E + j) * E + c];
            g_bfin[r * E + j] = s;
        }
    }
}

// ---------------- setup2: fp16 conversions + bv ----------------
// y 0..3 : panel-major wh[y][ks][n][perm l] = mfin[y][k][n]
// y 4..5 : same, with f_out_w fold
// y 6..11: row-major wh[y][n][perm k] = cproj[y-6][k][n]  (K2 path)
// y == 12 (n<2): bv
__global__ void setup2(const float* __restrict__ f_out_w, const float* __restrict__ f_out_b)
{
    __shared__ float s_fw[E];
    int y = blockIdx.y, n = blockIdx.x, k = threadIdx.x;
    if (y < 4) {
        g_wh[(size_t)y * E * E + (k >> 4) * 2560 + n * 16 + kperm(k & 15)] =
            __float2half(g_mfin[(size_t)y * E * E + k * E + n]);
    } else if (y < 6) {
        s_fw[k] = f_out_w[n * E + k];
        __syncthreads();
        const float* mrow = g_mfin + (size_t)y * E * E + k * E;
        float s = 0.f;
        #pragma unroll 8
        for (int j = 0; j < E; j++) s += mrow[j] * s_fw[j];
        g_wh[(size_t)y * E * E + (k >> 4) * 2560 + n * 16 + kperm(k & 15)] = __float2half(s);
    } else if (y < 12) {
        g_wh[(size_t)y * E * E + n * E + (k >> 4) * 16 + kperm(k & 15)] =
            __float2half(g_cproj[(size_t)(y - 6) * E * E + k * E + n]);
    } else {
        if (n < 2) {
            float s = f_out_b[k];
            const float* bf = g_bfin + (4 + n) * E;
            #pragma unroll 8
            for (int j = 0; j < E; j++) s += bf[j] * f_out_w[k * E + j];
            g_bv[n * E + k] = s;
        }
    }
}

// ---------------- 128x160 GEMM K=160, fp32, ELU out (K6) -------------
template<int TRANSB, int MODE>
__global__ __launch_bounds__(256, 1) void gemm128(
    const float* __restrict__ A, const float* __restrict__ Bm,
    const float* __restrict__ bias, float* __restrict__ Out)
{
    extern __shared__ float sm[];
    float* As = sm;
    float* Bs = sm + 128 * E;
    const int t = threadIdx.x;
    const size_t rowBase = (size_t)blockIdx.x * 128;

    const float4* Ag = reinterpret_cast<const float4*>(A + rowBase * E);
    float4* As4 = reinterpret_cast<float4*>(As);
    #pragma unroll
    for (int i = 0; i < 20; i++) As4[t + 256 * i] = Ag[t + 256 * i];

    if (TRANSB == 0) {
        #pragma unroll 4
        for (int i = 0; i < 100; i++) {
            int idx = t + 256 * i;
            int k = idx / E, j = idx - k * E;
            Bs[k * BSTR + j] = Bm[idx];
        }
    } else {
        #pragma unroll 4
        for (int i = 0; i < 100; i++) {
            int idx = t + 256 * i;
            int j = idx / E, k = idx - j * E;
            Bs[k * BSTR + j] = Bm[idx];
        }
    }
    __syncthreads();

    const int tx = t & 15, ty = t >> 4;
    unsigned long long acc[8][5];
    const unsigned long long z = pack2(0.f, 0.f);
    #pragma unroll
    for (int i = 0; i < 8; i++)
        #pragma unroll
        for (int u = 0; u < 5; u++) acc[i][u] = z;

    const float* Ath = As + ty * (8 * E);
    #pragma unroll 2
    for (int k = 0; k < E; k++) {
        unsigned long long b2[5];
        const unsigned long long* bp =
            reinterpret_cast<const unsigned long long*>(Bs + k * BSTR + tx * 10);
        #pragma unroll
        for (int u = 0; u < 5; u++) b2[u] = bp[u];
        #pragma unroll
        for (int i = 0; i < 8; i++) {
            float a = Ath[i * E + k];
            unsigned long long a2 = pack2(a, a);
            #pragma unroll
            for (int u = 0; u < 5; u++) acc[i][u] = fma2(a2, b2[u], acc[i][u]);
        }
    }

    float bcol[10];
    #pragma unroll
    for (int u = 0; u < 10; u++) bcol[u] = bias[tx * 10 + u];

    #pragma unroll
    for (int i = 0; i < 8; i++) {
        size_t ro = (rowBase + ty * 8 + i) * E + tx * 10;
        #pragma unroll
        for (int u = 0; u < 5; u++) {
            float2 v = unpack2(acc[i][u]);
            v.x += bcol[2 * u];
            v.y += bcol[2 * u + 1];
            if (MODE == 1) {
                v.x = v.x > 0.f ? v.x : expm1f(v.x);
                v.y = v.y > 0.f ? v.y : expm1f(v.y);
            }
            *reinterpret_cast<float2*>(Out + ro + 2 * u) = v;
        }
    }
}

// ---------------- K2: tensor-core merged projection of X (6 matrices) ----------
__global__ __launch_bounds__(256, 2) void gemm6_mma(
    const float* __restrict__ X,
    const float* __restrict__ i_in_b, const float* __restrict__ o_in_b)
{
    extern __shared__ uint32_t smw[];
    uint32_t* Aw = smw;                 // 128*84 words
    uint32_t* Bw = smw + 128 * 84;      // 160*84 words
    const int t = threadIdx.x;
    const size_t rowBase = (size_t)blockIdx.x * 128;

    {
        const float4* Xg = reinterpret_cast<const float4*>(X + rowBase * E);
        #pragma unroll
        for (int s = 0; s < 10; s++) {
            int idx = t + 256 * s;
            int row = idx / 20, c = idx - row * 20;
            float4 x0 = Xg[idx * 2], x1 = Xg[idx * 2 + 1];
            uint32_t* d = Aw + row * 84 + (c >> 1) * 8 + (c & 1);
            d[0] = H2F(x0.x, x0.y);
            d[2] = H2F(x0.z, x0.w);
            d[4] = H2F(x1.x, x1.y);
            d[6] = H2F(x1.z, x1.w);
        }
    }

    const int lane = t & 31, w = t >> 5;
    const int rb = (w >> 1) * 32;
    const int cb = (w & 1) * 80;
    const int g = lane >> 2, q = lane & 3;

    const uint32_t* A0 = Aw + (rb + g) * 84 + q * 2;
    const uint32_t* B0 = Bw + (cb + g) * 84 + q * 2;

    for (int p = 0; p < 6; p++) {
        __syncthreads();
        {
            const uint4* Bg = reinterpret_cast<const uint4*>(g_wh + (size_t)(6 + p) * E * E);
            #pragma unroll
            for (int s = 0; s < 13; s++) {
                int idx = t + 256 * s;
                if (idx < 3200) {
                    int n = idx / 20, c = idx - n * 20;
                    *reinterpret_cast<uint4*>(Bw + n * 84 + c * 4) = Bg[idx];
                }
            }
        }
        __syncthreads();

        float acc[2][10][4];
        #pragma unroll
        for (int h2 = 0; h2 < 2; h2++)
            #pragma unroll
            for (int j = 0; j < 10; j++)
                #pragma unroll
                for (int u = 0; u < 4; u++) acc[h2][j][u] = 0.f;

        #pragma unroll
        for (int ks = 0; ks < 10; ks++) {
            uint2 aA0 = *reinterpret_cast<const uint2*>(A0 + ks * 8);
            uint2 aB0 = *reinterpret_cast<const uint2*>(A0 + 8 * 84 + ks * 8);
            uint2 aA1 = *reinterpret_cast<const uint2*>(A0 + 16 * 84 + ks * 8);
            uint2 aB1 = *reinterpret_cast<const uint2*>(A0 + 24 * 84 + ks * 8);
            #pragma unroll
            for (int j = 0; j < 10; j++) {
                uint2 bb = *reinterpret_cast<const uint2*>(B0 + (j * 8) * 84 + ks * 8);
                mma16816(acc[0][j], aA0.x, aB0.x, aA0.y, aB0.y, bb.x, bb.y);
                mma16816(acc[1][j], aA1.x, aB1.x, aA1.y, aB1.y, bb.x, bb.y);
            }
        }

        const float* bias = (p < 3) ? (i_in_b + p * E) : (o_in_b + (p - 3) * E);
        __half* Outg = g_px + (size_t)p * BN * E + rowBase * E;
        __syncthreads();
        __half* stage = reinterpret_cast<__half*>(Bw);
        #pragma unroll
        for (int j = 0; j < 10; j++) {
            int col = cb + j * 8 + q * 2;
            float b0f = bias[col], b1f = bias[col + 1];
            #pragma unroll
            for (int h2 = 0; h2 < 2; h2++) {
                int row = rb + h2 * 16 + g;
                *reinterpret_cast<__half2*>(stage + row * 160 + col) =
                    __floats2half2_rn(acc[h2][j][0] + b0f, acc[h2][j][1] + b1f);
                *reinterpret_cast<__half2*>(stage + (row + 8) * 160 + col) =
                    __floats2half2_rn(acc[h2][j][2] + b0f, acc[h2][j][3] + b1f);
            }
        }
        __syncthreads();
        #pragma unroll
        for (int s = 0; s < 10; s++) {
            int idx = t + 256 * s;
            reinterpret_cast<uint4*>(Outg)[idx] =
                reinterpret_cast<const uint4*>(stage)[idx];
        }
    }
}

// ---------------- K3: inner attention via mma + ldmatrix (token-major obuf) ----
__global__ __launch_bounds__(320) void inner_attn_mma(const int* __restrict__ in_idx,
                                                      const int* __restrict__ out_idx)
{
    __shared__ __align__(16) __half tile[96][168];   // rows: hh*48 + mat*16 + l
    __shared__ int idxs[2][16];
    const int n = blockIdx.x, b = blockIdx.y;
    const int t = threadIdx.x;
    const size_t tok = (size_t)b * NN + n;
    const size_t base = (size_t)b * NN;

    if (t < 32) {
        int hh = t >> 4, i = t & 15;
        const int* ia = hh ? out_idx : in_idx;
        idxs[hh][i] = (i == 0) ? n : ia[tok * DINN + i - 1];
    }
    __syncthreads();

    #pragma unroll
    for (int it = 0; it < 6; it++) {
        int task = t + 320 * it;
        int r = task / 20, seg = task - r * 20;
        int hh = r / 48, sub = r - hh * 48;
        int mat = sub >> 4, l = sub & 15;
        const __half* src = g_px +
            ((size_t)(hh * 3 + mat) * BN + base + idxs[hh][l]) * E + seg * 8;
        *reinterpret_cast<uint4*>(&tile[r][seg * 8]) =
            *reinterpret_cast<const uint4*>(src);
    }
    __syncthreads();

    const int w = t >> 5, lane = t & 31;
    const int g = lane >> 2, q = lane & 3;
    const int hh = w / 5, h = w - hh * 5;
    const int qr = hh * 48, kr = qr + 16, vr = qr + 32;
    const int koff = h * 32;
    const int lrow = lane & 15, lcol = (lane >> 4) * 8;

    float s0[4] = {0.f, 0.f, 0.f, 0.f}, s1[4] = {0.f, 0.f, 0.f, 0.f};
    #pragma unroll
    for (int kc = 0; kc < 2; kc++) {
        int ko = koff + kc * 16;
        uint32_t a0, a1, a2, a3, k0, k1, k2, k3;
        ldsm_x4(a0, a1, a2, a3, cvta_smem(&tile[qr + lrow][ko + lcol]));
        ldsm_x4(k0, k1, k2, k3, cvta_smem(&tile[kr + lrow][ko + lcol]));
        mma16816(s0, a0, a1, a2, a3, k0, k2);
        mma16816(s1, a0, a1, a2, a3, k1, k3);
    }
    const float scale = 0.17677669529663687f;  // 1/sqrt(32)
    #pragma unroll
    for (int u = 0; u < 4; u++) { s0[u] *= scale; s1[u] *= scale; }

    float mx0 = fmaxf(fmaxf(s0[0], s0[1]), fmaxf(s1[0], s1[1]));
    float mx1 = fmaxf(fmaxf(s0[2], s0[3]), fmaxf(s1[2], s1[3]));
    mx0 = fmaxf(mx0, __shfl_xor_sync(0xffffffffu, mx0, 1));
    mx0 = fmaxf(mx0, __shfl_xor_sync(0xffffffffu, mx0, 2));
    mx1 = fmaxf(mx1, __shfl_xor_sync(0xffffffffu, mx1, 1));
    mx1 = fmaxf(mx1, __shfl_xor_sync(0xffffffffu, mx1, 2));
    float e00 = __expf(s0[0] - mx0), e01 = __expf(s0[1] - mx0);
    float e02 = __expf(s1[0] - mx0), e03 = __expf(s1[1] - mx0);
    float e10 = __expf(s0[2] - mx1), e11 = __expf(s0[3] - mx1);
    float e12 = __expf(s1[2] - mx1), e13 = __expf(s1[3] - mx1);
    float sum0 = e00 + e01 + e02 + e03;
    float sum1 = e10 + e11 + e12 + e13;
    sum0 += __shfl_xor_sync(0xffffffffu, sum0, 1);
    sum0 += __shfl_xor_sync(0xffffffffu, sum0, 2);
    sum1 += __shfl_xor_sync(0xffffffffu, sum1, 1);
    sum1 += __shfl_xor_sync(0xffffffffu, sum1, 2);
    float inv0 = 1.f / sum0, inv1 = 1.f / sum1;

    uint32_t pa0 = H2F(e00 * inv0, e01 * inv0);
    uint32_t pa1 = H2F(e10 * inv1, e11 * inv1);
    uint32_t pa2 = H2F(e02 * inv0, e03 * inv0);
    uint32_t pa3 = H2F(e12 * inv1, e13 * inv1);

    // token-major obuf: token rows [32*tok, +32), half hh at +16*hh
    __half* ob = g_obuf + ((size_t)tok * 32 + hh * 16) * E + koff;
    #pragma unroll
    for (int nt = 0; nt < 4; nt++) {
        uint32_t b0, b1;
        ldsm_x2t(b0, b1, cvta_smem(&tile[vr + lrow][koff + nt * 8]));
        float o[4] = {0.f, 0.f, 0.f, 0.f};
        mma16816(o, pa0, pa1, pa2, pa3, b0, b1);
        *reinterpret_cast<__half2*>(ob + (size_t)g * E + nt * 8 + 2 * q) =
            __floats2half2_rn(o[0], o[1]);
        *reinterpret_cast<__half2*>(ob + (size_t)(g + 8) * E + nt * 8 + 2 * q) =
            __floats2half2_rn(o[2], o[3]);
    }
}

// ---------------- K45 fused v3: distance-2 B register pipeline -----------------
// CTA = 2 tokens = 64 obuf rows. B fragments stream from panel-major g_wh into
// 3 rotating register buffers (prefetch distance 2) -> deeper latency hiding.
// Q/K/V' land in smem; attention tail identical to validated R12/R13 code.
// smem layout (bytes):
//   [0, 21504)        A (64 rows x 84 words, k-permuted)  -- reused for sc/ps/pb
//   [21504, 43008)    Qs  (64 x 168 halves)
//   [43008, 64512)    Ks
//   [64512, 86016)    Vs
#define FA_SMEM 86016
__global__ __launch_bounds__(256, 2) void fused_attn()
{
    extern __shared__ __align__(16) char smc[];
    uint32_t* Aw   = reinterpret_cast<uint32_t*>(smc);
    __half (*Qs)[168] = reinterpret_cast<__half(*)[168]>(smc + 21504);
    __half (*Ks)[168] = reinterpret_cast<__half(*)[168]>(smc + 43008);
    __half (*Vs)[168] = reinterpret_cast<__half(*)[168]>(smc + 64512);

    const int t = threadIdx.x;
    const size_t rowBase = (size_t)blockIdx.x * 64;

    // ---- load A tile (64 rows fp16, k-permuted store) ----
    {
        const uint4* Ag = reinterpret_cast<const uint4*>(g_obuf + rowBase * E);
        #pragma unroll
        for (int s = 0; s < 5; s++) {
            int idx = t + 256 * s;
            int row = idx / 20, c = idx - row * 20;
            uint4 v = Ag[idx];
            uint32_t* d = Aw + row * 84 + (c >> 1) * 8 + (c & 1);
            d[0] = v.x; d[2] = v.y; d[4] = v.z; d[6] = v.w;
        }
    }

    const int lane = t & 31, w = t >> 5;
    const int g = lane >> 2, q = lane & 3;
    const int half = w >> 2;             // GEMM: which half's weight matrix
    const int cb = (w & 3) * 40;         // GEMM: 40-col group
    const uint32_t* A0 = Aw + (half * 16 + g) * 84 + q * 2;
    // lane's half-element offset within a k-panel (coalesced across warp)
    const int boff = (cb + g) * 16 + q * 4;

    __syncthreads();   // A tile ready

    #pragma unroll 1
    for (int p = 0; p < 3; p++) {
        const __half* Wb = g_wh + (size_t)(2 * p + half) * E * E;

        // prefetch panels 0 and 1 into register buffers 0,1 (distance-2 pipeline)
        uint2 bb[3][5];
        #pragma unroll
        for (int j = 0; j < 5; j++) {
            bb[0][j] = *reinterpret_cast<const uint2*>(Wb + boff + j * 128);
            bb[1][j] = *reinterpret_cast<const uint2*>(Wb + 2560 + boff + j * 128);
        }

        float acc[2][5][4];
        #pragma unroll
        for (int h2 = 0; h2 < 2; h2++)
            #pragma unroll
            for (int j = 0; j < 5; j++)
                #pragma unroll
                for (int u = 0; u < 4; u++) acc[h2][j][u] = 0.f;

        #pragma unroll
        for (int ks = 0; ks < 10; ks++) {
            const int cur = ks % 3;          // constant under full unroll
            if (ks < 8) {
                const int nxt = (ks + 2) % 3;
                const __half* Wn = Wb + (ks + 2) * 2560 + boff;
                #pragma unroll
                for (int j = 0; j < 5; j++)
                    bb[nxt][j] = *reinterpret_cast<const uint2*>(Wn + j * 128);
            }
            uint2 aA0 = *reinterpret_cast<const uint2*>(A0 + ks * 8);
            uint2 aB0 = *reinterpret_cast<const uint2*>(A0 + 8 * 84 + ks * 8);
            uint2 aA1 = *reinterpret_cast<const uint2*>(A0 + 32 * 84 + ks * 8);
            uint2 aB1 = *reinterpret_cast<const uint2*>(A0 + 40 * 84 + ks * 8);
            #pragma unroll
            for (int j = 0; j < 5; j++) {
                mma16816(acc[0][j], aA0.x, aB0.x, aA0.y, aB0.y, bb[cur][j].x, bb[cur][j].y);
                mma16816(acc[1][j], aA1.x, aB1.x, aA1.y, aB1.y, bb[cur][j].x, bb[cur][j].y);
            }
        }

        // epilogue: bias + fp16 into Qs/Ks/Vs (disjoint per-warp regions; no sync)
        {
            const float* bias = (p < 2) ? (g_bfin + (2 * p + half) * E)
                                        : (g_bv + half * E);
            __half (*dst)[168] = (p == 0) ? Qs : (p == 1) ? Ks : Vs;
            const int r0 = half * 16 + g;
            #pragma unroll
            for (int j = 0; j < 5; j++) {
                int col = cb + j * 8 + 2 * q;
                float b0f = bias[col], b1f = bias[col + 1];
                *reinterpret_cast<__half2*>(&dst[r0][col]) =
                    __floats2half2_rn(acc[0][j][0] + b0f, acc[0][j][1] + b1f);
                *reinterpret_cast<__half2*>(&dst[r0 + 8][col]) =
                    __floats2half2_rn(acc[0][j][2] + b0f, acc[0][j][3] + b1f);
                *reinterpret_cast<__half2*>(&dst[32 + r0][col]) =
                    __floats2half2_rn(acc[1][j][0] + b0f, acc[1][j][1] + b1f);
                *reinterpret_cast<__half2*>(&dst[32 + r0 + 8][col]) =
                    __floats2half2_rn(acc[1][j][2] + b0f, acc[1][j][3] + b1f);
            }
        }
    }
    __syncthreads();   // Q/K/V complete, A region free

    // ---- attention on the 2 tokens (Q/K/V in smem) ----
    float*  sc = reinterpret_cast<float*>(smc);            // [2][32][34]
    __half* ps = reinterpret_cast<__half*>(smc + 8704);    // [2][32][40]
    float*  pb = reinterpret_cast<float*>(smc + 13824);    // [2][2][160]

    const int lrow = lane & 15, lcol = (lane >> 4) * 8;

    // scores: warp -> (token w>>2, mt=(w>>1)&1, nt2=w&1), m16n16, k=160
    {
        const int tk = w >> 2, mt = (w >> 1) & 1, nt2 = w & 1;
        const __half* Qb = &Qs[32 * tk + 16 * mt + lrow][0];
        const __half* Kb = &Ks[32 * tk + 16 * nt2 + lrow][0];
        float s0[4] = {0.f, 0.f, 0.f, 0.f}, s1[4] = {0.f, 0.f, 0.f, 0.f};
        #pragma unroll
        for (int kc = 0; kc < 10; kc++) {
            uint32_t a0, a1, a2, a3, k0, k1, k2, k3;
            ldsm_x4(a0, a1, a2, a3, cvta_smem(Qb + kc * 16 + lcol));
            ldsm_x4(k0, k1, k2, k3, cvta_smem(Kb + kc * 16 + lcol));
            mma16816(s0, a0, a1, a2, a3, k0, k2);
            mma16816(s1, a0, a1, a2, a3, k1, k3);
        }
        const float scale = 0.07905694150420949f;  // 1/sqrt(160)
        float* scr = sc + tk * (32 * 34);
        int rr = 16 * mt + g, cc = 16 * nt2 + 2 * q;
        *reinterpret_cast<float2*>(&scr[rr * 34 + cc]) =
            make_float2(s0[0] * scale, s0[1] * scale);
        *reinterpret_cast<float2*>(&scr[(rr + 8) * 34 + cc]) =
            make_float2(s0[2] * scale, s0[3] * scale);
        *reinterpret_cast<float2*>(&scr[rr * 34 + cc + 8]) =
            make_float2(s1[0] * scale, s1[1] * scale);
        *reinterpret_cast<float2*>(&scr[(rr + 8) * 34 + cc + 8]) =
            make_float2(s1[2] * scale, s1[3] * scale);
    }
    __syncthreads();

    // softmax: 64 threads, one row each
    if (t < 64) {
        const int tk = t >> 5, r = t & 31;
        float* row = sc + tk * (32 * 34) + r * 34;
        float v[32];
        float mx = -3.4e38f;
        #pragma unroll
        for (int m = 0; m < 32; m++) { v[m] = row[m]; mx = fmaxf(mx, v[m]); }
        float sum = 0.f;
        #pragma unroll
        for (int m = 0; m < 32; m++) { v[m] = __expf(v[m] - mx); sum += v[m]; }
        float inv = 1.f / sum;
        __half* pr = ps + tk * (32 * 40) + r * 40;
        #pragma unroll
        for (int m = 0; m < 16; m++)
            *reinterpret_cast<__half2*>(pr + 2 * m) =
                __floats2half2_rn(v[2 * m] * inv, v[2 * m + 1] * inv);
    }
    __syncthreads();

    // AV + max pool: warp -> (token w>>2, mt, nb), m16n80 (10 n-tiles per warp)
    {
        const int tk = w >> 2, sub = w & 3;
        const int mt = sub >> 1, nb = sub & 1;
        uint32_t a[2][4];
        #pragma unroll
        for (int kc = 0; kc < 2; kc++)
            ldsm_x4(a[kc][0], a[kc][1], a[kc][2], a[kc][3],
                    cvta_smem(ps + tk * (32 * 40) + (16 * mt + lrow) * 40 + kc * 16 + lcol));
        #pragma unroll
        for (int nt = 0; nt < 10; nt++) {
            float o[4] = {0.f, 0.f, 0.f, 0.f};
            #pragma unroll
            for (int kc = 0; kc < 2; kc++) {
                uint32_t b0, b1;
                ldsm_x2t(b0, b1, cvta_smem(&Vs[32 * tk + kc * 16 + lrow][nb * 80 + nt * 8]));
                mma16816(o, a[kc][0], a[kc][1], a[kc][2], a[kc][3], b0, b1);
            }
            float m0 = fmaxf(o[0], o[2]);
            float m1 = fmaxf(o[1], o[3]);
            #pragma unroll
            for (int s = 4; s < 32; s <<= 1) {
                m0 = fmaxf(m0, __shfl_xor_sync(0xffffffffu, m0, s));
                m1 = fmaxf(m1, __shfl_xor_sync(0xffffffffu, m1, s));
            }
            if (g == 0)
                *reinterpret_cast<float2*>(&pb[(tk * 2 + mt) * 160 + nb * 80 + nt * 8 + 2 * q]) =
                    make_float2(m0, m1);
        }
    }
    __syncthreads();

    // final pool across the two 16-row halves -> g_pooled
    for (int j = t; j < 320; j += 256) {
        int tk = j / 160, c = j - tk * 160;
        g_pooled[((size_t)blockIdx.x * 2 + tk) * E + c] =
            fmaxf(pb[tk * 320 + c], pb[tk * 320 + 160 + c]);
    }
}

// ---------------- host orchestration ----------------
extern "C" void kernel_launch(void* const* d_in, const int* in_sizes, int n_in,
                              void* d_out, int out_size)
{
    const float* X       = (const float*)d_in[0];
    const int*   in_idx  = (const int*)  d_in[1];
    const int*   out_idx = (const int*)  d_in[2];
    const float* iWq     = (const float*)d_in[3];
    const float* iWk     = (const float*)d_in[4];
    const float* iWv     = (const float*)d_in[5];
    const float* i_in_w  = (const float*)d_in[6];
    const float* i_in_b  = (const float*)d_in[7];
    const float* i_out_w = (const float*)d_in[8];
    const float* i_out_b = (const float*)d_in[9];
    const float* oWq     = (const float*)d_in[10];
    const float* oWk     = (const float*)d_in[11];
    const float* oWv     = (const float*)d_in[12];
    const float* o_in_w  = (const float*)d_in[13];
    const float* o_in_b  = (const float*)d_in[14];
    const float* o_out_w = (const float*)d_in[15];
    const float* o_out_b = (const float*)d_in[16];
    const float* f_in_w  = (const float*)d_in[17];
    const float* f_in_b  = (const float*)d_in[18];
    const float* f_out_w = (const float*)d_in[19];
    const float* f_out_b = (const float*)d_in[20];
    const float* lin_w   = (const float*)d_in[21];
    const float* lin_b   = (const float*)d_in[22];
    float* out = (float*)d_out;

    float* pooled;
    cudaGetSymbolAddress((void**)&pooled, g_pooled);

    const size_t smem_g   = (size_t)(128 * E + E * BSTR) * sizeof(float);   // 185,600 B
    const size_t smem_mma = (size_t)(128 * 84 + 160 * 84) * 4;              //  96,768 B
    cudaFuncSetAttribute(gemm128<1, 1>, cudaFuncAttributeMaxDynamicSharedMemorySize, (int)smem_g);
    cudaFuncSetAttribute(gemm6_mma,     cudaFuncAttributeMaxDynamicSharedMemorySize, (int)smem_mma);
    cudaFuncSetAttribute(fused_attn,    cudaFuncAttributeMaxDynamicSharedMemorySize, FA_SMEM);

    // K1: fused weights + biases (2 launches)
    setup1<<<dim3(E, 13), E>>>(iWq, iWk, iWv, oWq, oWk, oWv,
                               i_in_w, o_in_w, f_in_w, i_out_w, o_out_w,
                               f_in_b, i_out_b, o_out_b);
    setup2<<<dim3(E, 13), E>>>(f_out_w, f_out_b);

    // K2: merged tensor-core projection of X -> px (fp16), one launch
    gemm6_mma<<<BN / 128, 256, smem_mma>>>(X, i_in_b, o_in_b);

    // K3: inner attentions via tensor cores -> obuf (token-major fp16)
    inner_attn_mma<<<dim3(NN, BB), 320>>>(in_idx, out_idx);

    // K45: fused final projections (distance-2 pipeline) + attention + max pool
    fused_attn<<<BN / 2, 256, FA_SMEM>>>();

    // K6: pooled @ lin_w.T + lin_b, ELU -> output
    gemm128<1, 1><<<BN / 128, 256, smem_g>>>(pooled, lin_w, lin_b, out);

    (void)in_sizes; (void)n_in; (void)out_size;
}